// round 11
// baseline (speedup 1.0000x reference)
#include <cuda_runtime.h>
#include <cuda_fp16.h>
#include <cstdint>

// Problem constants
#define B_    16
#define CC    256
#define HW    4096
#define NTOK  65536
#define NE    1024
#define D     256
#define ZQ_ELEMS (NTOK * CC)
#define LOSS_OFF ZQ_ELEMS
#define CLS_OFF  (ZQ_ELEMS + 1)
#define IDX_OFF  (ZQ_ELEMS + 2)
#define GRID_C 2048

#define MARGIN 1.0f      // > 2x worst-case fp16 screening error; validated R8/R10
#define KCAND  64        // per-token candidate cap (expected ~18)

// Pass-1 tiling: CTA = 128 tokens x NE codes, j-tiles of 64, k-chunks of 64
#define TM   128
#define JT   64
#define KC   64
#define NCHUNK 64            // 16 j-tiles * 4 k-chunks

// Pass-1 smem layout (bytes)
#define AS_PITCH_H 264       // halves per token row (256 + 8 pad); 528 B pitch
#define OFF_AS 0             // half As[128][264] = 67584
#define BS_PITCH_U 36        // uint (half2) per code row (32 + 4 pad); 144 B pitch
#define BS_SZ  9216          // 64 * 36 * 4
#define OFF_BS 67584         // two stages
#define OFF_CN (67584 + 2 * BS_SZ)     // 86016
#define OFF_CNT (OFF_CN + 4096)        // 90112 : int cnt[128]
#define OFF_CAND (OFF_CNT + 512)       // 90624 : ushort cand[128][KCAND]
#define P1_SMEM (OFF_CAND + TM * KCAND * 2)   // 107008

// Fused argmin+gather smem layout (bytes)
#define ZS_PITCH 261                    // odd -> conflict-free across tokens
#define AG_OFF_ZQ (32 * ZS_PITCH * 4)   // 33408
#define AG_OFF_IDX (AG_OFF_ZQ + 32 * 257 * 4)  // 66304
#define AG_OFF_WS (AG_OFF_IDX + 128)    // 66432
#define AG_SMEM (AG_OFF_WS + 32)        // 66464

// Scratch (static device arrays are the sanctioned workaround)
__device__ int            g_cnt[NTOK];
__device__ unsigned short g_cand[(size_t)NTOK * KCAND];   // 8 MB
__device__ float          g_cnorm[NE];
__device__ float          g_partial[GRID_C];

// ---------------------------------------------------------------------------
// helpers
// ---------------------------------------------------------------------------
__device__ __forceinline__ uint32_t smem_u32(const void* p) {
    uint32_t a;
    asm("{ .reg .u64 t; cvta.to.shared.u64 t, %1; cvt.u32.u64 %0, t; }"
        : "=r"(a) : "l"(p));
    return a;
}
__device__ __forceinline__ uint32_t pack_h2(float x, float y) {
    __half2 h = __floats2half2_rn(x, y);
    return *reinterpret_cast<uint32_t*>(&h);
}
__device__ __forceinline__ void mma_h16(float& d0, float& d1, float& d2, float& d3,
                                        uint32_t a0, uint32_t a1, uint32_t a2, uint32_t a3,
                                        uint32_t b0, uint32_t b1) {
    asm volatile(
        "mma.sync.aligned.m16n8k16.row.col.f32.f16.f16.f32 "
        "{%0,%1,%2,%3}, {%4,%5,%6,%7}, {%8,%9}, {%0,%1,%2,%3};\n"
        : "+f"(d0), "+f"(d1), "+f"(d2), "+f"(d3)
        : "r"(a0), "r"(a1), "r"(a2), "r"(a3), "r"(b0), "r"(b1));
}
__device__ __forceinline__ void ldm_x4(uint32_t& r0, uint32_t& r1,
                                       uint32_t& r2, uint32_t& r3, uint32_t addr) {
    asm volatile("ldmatrix.sync.aligned.m8n8.x4.shared.b16 {%0,%1,%2,%3}, [%4];"
                 : "=r"(r0), "=r"(r1), "=r"(r2), "=r"(r3) : "r"(addr));
}

// ---------------------------------------------------------------------------
// Kernel 1: per-code squared norms (warp per row)
// ---------------------------------------------------------------------------
__global__ void __launch_bounds__(256) cnorm_kernel(const float* __restrict__ cb) {
    int row  = blockIdx.x * 8 + (threadIdx.x >> 5);
    int lane = threadIdx.x & 31;
    const float* p = cb + (size_t)row * D;
    float s = 0.f;
    for (int k = lane; k < D; k += 32) { float v = p[k]; s = fmaf(v, v, s); }
    #pragma unroll
    for (int o = 16; o; o >>= 1) s += __shfl_xor_sync(0xffffffffu, s, o);
    if (lane == 0) g_cnorm[row] = s;
}

// ---------------------------------------------------------------------------
// Kernel 2 (pass 1): fp16 HMMA screening + fused candidate selection.
// ldmatrix.x4 fragment loads (A: token rows pitch 528B; B: code rows pitch
// 144B; both conflict-free). Candidate push per j-tile with running-min
// threshold (superset of the R8-validated global-threshold set).
// ---------------------------------------------------------------------------
__global__ void __launch_bounds__(256, 2) dist_kernel(const float* __restrict__ z,
                                                      const float* __restrict__ cb) {
    extern __shared__ char smem[];
    __half*         As_h  = (__half*)(smem + OFF_AS);
    float*          cnS   = (float*)(smem + OFF_CN);
    int*            sCnt  = (int*)(smem + OFF_CNT);
    unsigned short* sCand = (unsigned short*)(smem + OFF_CAND);

    const int tid  = threadIdx.x;
    const int w    = tid >> 5;
    const int lane = tid & 31;
    const int r    = lane >> 2;      // row-in-frag 0..7
    const int q    = lane & 3;       // quad column 0..3

    const int n0  = blockIdx.x * TM;
    const int b   = n0 >> 12;
    const int rem = n0 & (HW - 1);

    // Stage A: z[b, k, rem+t] -> half As[t][k]  (coalesced loads over t)
    for (int i = tid; i < D * TM / 4; i += 256) {
        int k  = i >> 5;
        int t4 = (i & 31) * 4;
        float4 v = *(const float4*)(z + (size_t)b * CC * HW + (size_t)k * HW + rem + t4);
        As_h[(t4 + 0) * AS_PITCH_H + k] = __float2half_rn(v.x);
        As_h[(t4 + 1) * AS_PITCH_H + k] = __float2half_rn(v.y);
        As_h[(t4 + 2) * AS_PITCH_H + k] = __float2half_rn(v.z);
        As_h[(t4 + 3) * AS_PITCH_H + k] = __float2half_rn(v.w);
    }
    for (int i = tid; i < NE; i += 256) cnS[i] = g_cnorm[i];
    for (int i = tid; i < TM; i += 256) sCnt[i] = 0;

    // B staging task: thread -> (n = tid>>2, kq = tid&3), 16 floats
    const int bn  = tid >> 2;
    const int bkq = tid & 3;

    // prefetch chunk 0
    float4 pf[4];
    {
        const float* src = cb + (size_t)bn * D + bkq * 16;
        #pragma unroll
        for (int u = 0; u < 4; u++) pf[u] = *(const float4*)(src + u * 4);
        uint32_t* Bs = (uint32_t*)(smem + OFF_BS);
        #pragma unroll
        for (int u = 0; u < 4; u++) {
            Bs[bn * BS_PITCH_U + bkq * 8 + u * 2 + 0] = pack_h2(-2.f * pf[u].x, -2.f * pf[u].y);
            Bs[bn * BS_PITCH_U + bkq * 8 + u * 2 + 1] = pack_h2(-2.f * pf[u].z, -2.f * pf[u].w);
        }
    }
    __syncthreads();

    float acc[8][4];
    #pragma unroll
    for (int nt = 0; nt < 8; nt++)
        #pragma unroll
        for (int c = 0; c < 4; c++) acc[nt][c] = 0.f;

    const int t0 = w * 16;
    const int tA = t0 + r;         // local token owned via acc[.][0..1]
    const int tB = tA + 8;         // local token owned via acc[.][2..3]
    float curMin0 = 3.4e38f, curMin1 = 3.4e38f;

    // ldmatrix per-thread address components
    const uint32_t aAddrBase = smem_u32(smem + OFF_AS)
                             + (uint32_t)(t0 + (lane & 15)) * 528
                             + (uint32_t)((lane >> 4) * 16);
    const uint32_t bOff = (uint32_t)((lane & 7) * 144 + ((lane >> 3) & 1) * 16);
    const uint32_t bSel = (uint32_t)(lane >> 4);     // 0 or 1 -> nt within pair

    for (int g = 0; g < NCHUNK; g++) {
        const int jt = g >> 2;
        const int kc = g & 3;

        // prefetch next chunk's B from global
        if (g + 1 < NCHUNK) {
            const int j0n = ((g + 1) >> 2) * JT;
            const int kbn = ((g + 1) & 3) * KC;
            const float* src = cb + (size_t)(j0n + bn) * D + kbn + bkq * 16;
            #pragma unroll
            for (int u = 0; u < 4; u++) pf[u] = *(const float4*)(src + u * 4);
        }

        // compute chunk g from stage g&1 via ldmatrix fragments
        const uint32_t sbB = smem_u32(smem + OFF_BS + (g & 1) * BS_SZ);
        #pragma unroll
        for (int s = 0; s < 4; s++) {
            uint32_t a0, a1, a2, a3;
            ldm_x4(a0, a1, a2, a3, aAddrBase + (uint32_t)(kc * 128 + s * 32));
            #pragma unroll
            for (int p = 0; p < 4; p++) {
                uint32_t b0, b1, b2, b3;
                ldm_x4(b0, b1, b2, b3,
                       sbB + (2u * p + bSel) * 1152u + bOff + (uint32_t)(s * 32));
                mma_h16(acc[2*p][0],   acc[2*p][1],   acc[2*p][2],   acc[2*p][3],
                        a0, a1, a2, a3, b0, b1);
                mma_h16(acc[2*p+1][0], acc[2*p+1][1], acc[2*p+1][2], acc[2*p+1][3],
                        a0, a1, a2, a3, b2, b3);
            }
        }

        // store next chunk into the other stage
        if (g + 1 < NCHUNK) {
            uint32_t* Bs2 = (uint32_t*)(smem + OFF_BS + ((g + 1) & 1) * BS_SZ);
            #pragma unroll
            for (int u = 0; u < 4; u++) {
                Bs2[bn * BS_PITCH_U + bkq * 8 + u * 2 + 0] = pack_h2(-2.f * pf[u].x, -2.f * pf[u].y);
                Bs2[bn * BS_PITCH_U + bkq * 8 + u * 2 + 1] = pack_h2(-2.f * pf[u].z, -2.f * pf[u].w);
            }
        }
        __syncthreads();

        // end of j-tile: running-min update + candidate pushes
        if (kc == 3) {
            const int jbase = jt * JT + 2 * q;
            float mn0 = 3.4e38f, mn1 = 3.4e38f;
            #pragma unroll
            for (int nt = 0; nt < 8; nt++) {
                int j = jbase + nt * 8;
                float c0 = cnS[j], c1 = cnS[j + 1];
                mn0 = fminf(mn0, fminf(c0 + acc[nt][0], c1 + acc[nt][1]));
                mn1 = fminf(mn1, fminf(c0 + acc[nt][2], c1 + acc[nt][3]));
            }
            // quad reduce (lanes r*4 .. r*4+3 are consecutive)
            mn0 = fminf(mn0, __shfl_xor_sync(0xffffffffu, mn0, 1));
            mn0 = fminf(mn0, __shfl_xor_sync(0xffffffffu, mn0, 2));
            mn1 = fminf(mn1, __shfl_xor_sync(0xffffffffu, mn1, 1));
            mn1 = fminf(mn1, __shfl_xor_sync(0xffffffffu, mn1, 2));
            curMin0 = fminf(curMin0, mn0);
            curMin1 = fminf(curMin1, mn1);
            const float thr0 = curMin0 + MARGIN;
            const float thr1 = curMin1 + MARGIN;
            #pragma unroll
            for (int nt = 0; nt < 8; nt++) {
                int j = jbase + nt * 8;
                float c0 = cnS[j], c1 = cnS[j + 1];
                if (c0 + acc[nt][0] < thr0) {
                    int pos = atomicAdd(&sCnt[tA], 1);
                    if (pos < KCAND) sCand[tA * KCAND + pos] = (unsigned short)j;
                }
                if (c1 + acc[nt][1] < thr0) {
                    int pos = atomicAdd(&sCnt[tA], 1);
                    if (pos < KCAND) sCand[tA * KCAND + pos] = (unsigned short)(j + 1);
                }
                if (c0 + acc[nt][2] < thr1) {
                    int pos = atomicAdd(&sCnt[tB], 1);
                    if (pos < KCAND) sCand[tB * KCAND + pos] = (unsigned short)j;
                }
                if (c1 + acc[nt][3] < thr1) {
                    int pos = atomicAdd(&sCnt[tB], 1);
                    if (pos < KCAND) sCand[tB * KCAND + pos] = (unsigned short)(j + 1);
                }
                acc[nt][0] = acc[nt][1] = acc[nt][2] = acc[nt][3] = 0.f;
            }
        }
    }

    // write lists to global (coalesced)
    __syncthreads();
    for (int i = tid; i < TM; i += 256) g_cnt[n0 + i] = sCnt[i];
    {
        const uint32_t* cu = (const uint32_t*)sCand;                 // [128][KCAND/2]
        uint32_t* gu = (uint32_t*)g_cand + (size_t)n0 * (KCAND / 2);
        for (int i = tid; i < TM * (KCAND / 2); i += 256) gu[i] = cu[i];
    }
}

// ---------------------------------------------------------------------------
// Kernel 3: fused exact argmin (candidate rescore) + gather + loss.
// Block = 32 tokens. z staged once in smem and reused for both the rescore
// dots and the straight-through output. Overflow (cnt > KCAND) -> full scan.
// ---------------------------------------------------------------------------
__global__ void __launch_bounds__(256) argmin_gather_kernel(const float* __restrict__ z,
                                                            const float* __restrict__ cb,
                                                            float* __restrict__ dout) {
    extern __shared__ char smem[];
    float* zs   = (float*)smem;                   // [32][ZS_PITCH]
    float* zq   = (float*)(smem + AG_OFF_ZQ);     // [32][257]
    int*   idxs = (int*)(smem + AG_OFF_IDX);
    float* ws   = (float*)(smem + AG_OFF_WS);

    const int tid  = threadIdx.x;
    const int w    = tid >> 5;
    const int lane = tid & 31;

    const int n0  = blockIdx.x * 32;
    const int b   = n0 >> 12;
    const int hw0 = n0 & (HW - 1);

    // stage z tile [t][k]
    for (int i = tid; i < D * 32 / 4; i += 256) {
        int k  = i >> 3;
        int t4 = (i & 7) * 4;
        float4 v = *(const float4*)(z + (size_t)b * CC * HW + (size_t)k * HW + hw0 + t4);
        zs[(t4 + 0) * ZS_PITCH + k] = v.x;
        zs[(t4 + 1) * ZS_PITCH + k] = v.y;
        zs[(t4 + 2) * ZS_PITCH + k] = v.z;
        zs[(t4 + 3) * ZS_PITCH + k] = v.w;
    }
    __syncthreads();

    // exact argmin over candidate lists (warp = 4 tokens)
    for (int tt = 0; tt < 4; tt++) {
        const int t = w * 4 + tt;
        const int n = n0 + t;
        const int cnt = g_cnt[n];

        float best = 3.4e38f;
        int   bi   = 0;
        if (cnt <= KCAND) {
            const unsigned short* lst = g_cand + (size_t)n * KCAND;
            for (int ci = 0; ci < cnt; ci++) {
                int j = lst[ci];
                const float* crow = cb + (size_t)j * D;
                float s = 0.f;
                #pragma unroll
                for (int u = 0; u < 8; u++)
                    s = fmaf(zs[t * ZS_PITCH + lane + 32 * u], crow[lane + 32 * u], s);
                #pragma unroll
                for (int o = 16; o; o >>= 1) s += __shfl_xor_sync(0xffffffffu, s, o);
                float dist = g_cnorm[j] - 2.0f * s;
                if (dist < best || (dist == best && j < bi)) { best = dist; bi = j; }
            }
        } else {
            // exact full scan (rare overflow fallback); ascending j, strict <
            for (int j = 0; j < NE; j++) {
                const float* crow = cb + (size_t)j * D;
                float s = 0.f;
                #pragma unroll
                for (int u = 0; u < 8; u++)
                    s = fmaf(zs[t * ZS_PITCH + lane + 32 * u], crow[lane + 32 * u], s);
                #pragma unroll
                for (int o = 16; o; o >>= 1) s += __shfl_xor_sync(0xffffffffu, s, o);
                float dist = g_cnorm[j] - 2.0f * s;
                if (dist < best) { best = dist; bi = j; }
            }
        }
        if (lane == 0) {
            idxs[t] = bi;
            dout[IDX_OFF + n] = (float)bi;
        }
    }
    __syncthreads();

    // load winning codebook rows (coalesced over channel)
    #pragma unroll 4
    for (int t = 0; t < 32; t++) {
        zq[t * 257 + tid] = cb[(size_t)idxs[t] * D + tid];
    }
    __syncthreads();

    // straight-through output + loss (z values come from the staged tile)
    const int t  = tid & 31;
    const int c0 = tid >> 5;
    float s = 0.f;
    float* ob = dout + (size_t)b * CC * HW + hw0 + t;
    #pragma unroll 8
    for (int it = 0; it < 32; it++) {
        int c = c0 * 32 + it;
        float zv = zs[t * ZS_PITCH + c];
        float d  = zq[t * 257 + c] - zv;
        ob[(size_t)c * HW] = zv + d;   // z + sg(z_q - z), exact fp32 expr
        s = fmaf(d, d, s);
    }

    #pragma unroll
    for (int o = 16; o; o >>= 1) s += __shfl_xor_sync(0xffffffffu, s, o);
    if ((tid & 31) == 0) ws[tid >> 5] = s;
    __syncthreads();
    if (tid < 8) {
        float v = ws[tid];
        #pragma unroll
        for (int o = 4; o; o >>= 1) v += __shfl_xor_sync(0xffu, v, o);
        if (tid == 0) g_partial[blockIdx.x] = v;
    }
}

// ---------------------------------------------------------------------------
// Kernel 4: deterministic final reduction
// ---------------------------------------------------------------------------
__global__ void __launch_bounds__(256) finalize_kernel(float* __restrict__ dout) {
    __shared__ float sh[256];
    float s = 0.f;
    for (int i = threadIdx.x; i < GRID_C; i += 256) s += g_partial[i];
    sh[threadIdx.x] = s;
    __syncthreads();
    for (int o = 128; o; o >>= 1) {
        if (threadIdx.x < o) sh[threadIdx.x] += sh[threadIdx.x + o];
        __syncthreads();
    }
    if (threadIdx.x == 0) {
        dout[LOSS_OFF] = sh[0] * (2.0f / (float)ZQ_ELEMS);
        dout[CLS_OFF]  = 0.0f;
    }
}

// ---------------------------------------------------------------------------
extern "C" void kernel_launch(void* const* d_in, const int* in_sizes, int n_in,
                              void* d_out, int out_size) {
    const float* z  = (const float*)d_in[0];   // [B,C,H,W] fp32
    const float* cb = (const float*)d_in[1];   // [NE, D]   fp32
    float* out = (float*)d_out;

    cudaFuncSetAttribute(dist_kernel,
                         cudaFuncAttributeMaxDynamicSharedMemorySize, P1_SMEM);
    cudaFuncSetAttribute(argmin_gather_kernel,
                         cudaFuncAttributeMaxDynamicSharedMemorySize, AG_SMEM);

    cnorm_kernel        <<<NE / 8, 256>>>(cb);
    dist_kernel         <<<NTOK / TM, 256, P1_SMEM>>>(z, cb);
    argmin_gather_kernel<<<NTOK / 32, 256, AG_SMEM>>>(z, cb, out);
    finalize_kernel     <<<1, 256>>>(out);
}

// round 13
// speedup vs baseline: 1.3520x; 1.3520x over previous
#include <cuda_runtime.h>
#include <cuda_fp16.h>
#include <cstdint>

// Problem constants
#define B_    16
#define CC    256
#define HW    4096
#define NTOK  65536
#define NE    1024
#define D     256
#define ZQ_ELEMS (NTOK * CC)
#define LOSS_OFF ZQ_ELEMS
#define CLS_OFF  (ZQ_ELEMS + 1)
#define IDX_OFF  (ZQ_ELEMS + 2)
#define GRID_C 2048

#define MARGIN 1.0f      // > 2x worst-case fp16 screening error; validated R8/R10
#define KCAND  64        // per-token candidate cap (expected ~18)

// Pass-1 tiling: CTA = 128 tokens x NE codes, j-tiles of 64, k-chunks of 64
// Warp tile: m32 x n32 (4 m-blocks x 2 n-blocks = 8 warps)
#define TM   128
#define JT   64
#define KC   64
#define NCHUNK 64            // 16 j-tiles * 4 k-chunks

// Pass-1 smem layout (bytes)
#define AS_PITCH_H 264       // halves per token row (256 + 8 pad)
#define AS_PITCH_U 132
#define OFF_AS 0             // half As[128][264] = 67584
#define BS_PITCH_U 36        // uint (half2) per code row (32 + 4 pad); 144 B
#define BS_SZ  9216          // 64 * 36 * 4
#define OFF_BS 67584         // two cp.async stages
#define OFF_CN (67584 + 2 * BS_SZ)     // 86016
#define OFF_CNT (OFF_CN + 4096)        // 90112 : int cnt[128]
#define OFF_CAND (OFF_CNT + 512)       // 90624 : ushort cand[128][KCAND]
#define P1_SMEM (OFF_CAND + TM * KCAND * 2)   // 107008 -> 2 CTAs/SM

// Scratch (static device arrays are the sanctioned workaround)
__device__ int            g_cnt[NTOK];
__device__ unsigned short g_cand[(size_t)NTOK * KCAND];   // 8 MB
__device__ int            g_idx[NTOK];
__device__ float          g_cnorm[NE];
__device__ float          g_partial[GRID_C];
__device__ __half         g_cbh[(size_t)NE * D];          // -2*codebook, fp16

// ---------------------------------------------------------------------------
// helpers
// ---------------------------------------------------------------------------
__device__ __forceinline__ uint32_t smem_u32(const void* p) {
    uint32_t a;
    asm("{ .reg .u64 t; cvta.to.shared.u64 t, %1; cvt.u32.u64 %0, t; }"
        : "=r"(a) : "l"(p));
    return a;
}
__device__ __forceinline__ void mma_h16(float& d0, float& d1, float& d2, float& d3,
                                        uint32_t a0, uint32_t a1, uint32_t a2, uint32_t a3,
                                        uint32_t b0, uint32_t b1) {
    asm volatile(
        "mma.sync.aligned.m16n8k16.row.col.f32.f16.f16.f32 "
        "{%0,%1,%2,%3}, {%4,%5,%6,%7}, {%8,%9}, {%0,%1,%2,%3};\n"
        : "+f"(d0), "+f"(d1), "+f"(d2), "+f"(d3)
        : "r"(a0), "r"(a1), "r"(a2), "r"(a3), "r"(b0), "r"(b1));
}
__device__ __forceinline__ void cp_async16(uint32_t dst, const void* src) {
    asm volatile("cp.async.cg.shared.global [%0], [%1], 16;"
                 :: "r"(dst), "l"(src) : "memory");
}
#define CP_COMMIT() asm volatile("cp.async.commit_group;" ::: "memory")
#define CP_WAIT0()  asm volatile("cp.async.wait_group 0;" ::: "memory")

// ---------------------------------------------------------------------------
// Kernel 1: per-code squared norms + fp16 pre-scaled codebook (-2*c)
// ---------------------------------------------------------------------------
__global__ void __launch_bounds__(256) cnorm_kernel(const float* __restrict__ cb) {
    int row  = blockIdx.x * 8 + (threadIdx.x >> 5);
    int lane = threadIdx.x & 31;
    const float* p = cb + (size_t)row * D;
    float s = 0.f;
    for (int k = lane; k < D; k += 32) {
        float v = p[k];
        s = fmaf(v, v, s);
        g_cbh[(size_t)row * D + k] = __float2half_rn(-2.f * v);
    }
    #pragma unroll
    for (int o = 16; o; o >>= 1) s += __shfl_xor_sync(0xffffffffu, s, o);
    if (lane == 0) g_cnorm[row] = s;
}

// ---------------------------------------------------------------------------
// Kernel 2 (pass 1): fp16 HMMA screening + fused candidate selection.
// m32n32 warp tiles (crossbar 64KB/chunk/CTA); B staged via 2-stage cp.async
// from the pre-scaled fp16 codebook (no cvt/pack chains). Candidate push per
// j-tile with per-warp-half running-min threshold (superset of the validated
// global-threshold set -> exactness preserved by pass 2).
// ---------------------------------------------------------------------------
__global__ void __launch_bounds__(256, 2) dist_kernel(const float* __restrict__ z) {
    extern __shared__ char smem[];
    __half*         As_h  = (__half*)(smem + OFF_AS);
    uint32_t*       As_u  = (uint32_t*)(smem + OFF_AS);
    float*          cnS   = (float*)(smem + OFF_CN);
    int*            sCnt  = (int*)(smem + OFF_CNT);
    unsigned short* sCand = (unsigned short*)(smem + OFF_CAND);

    const int tid  = threadIdx.x;
    const int w    = tid >> 5;
    const int lane = tid & 31;
    const int r    = lane >> 2;      // row-in-frag 0..7
    const int q    = lane & 3;       // quad column 0..3

    const int mbase = (w & 3) * 32;  // warp's 32-token block
    const int nblk  = w >> 2;        // warp's 32-code half of the j-tile

    const int n0  = blockIdx.x * TM;
    const int b   = n0 >> 12;
    const int rem = n0 & (HW - 1);

    // Stage A: z[b, k, rem+t] -> half As[t][k]  (coalesced loads over t)
    for (int i = tid; i < D * TM / 4; i += 256) {
        int k  = i >> 5;
        int t4 = (i & 31) * 4;
        float4 v = *(const float4*)(z + (size_t)b * CC * HW + (size_t)k * HW + rem + t4);
        As_h[(t4 + 0) * AS_PITCH_H + k] = __float2half_rn(v.x);
        As_h[(t4 + 1) * AS_PITCH_H + k] = __float2half_rn(v.y);
        As_h[(t4 + 2) * AS_PITCH_H + k] = __float2half_rn(v.z);
        As_h[(t4 + 3) * AS_PITCH_H + k] = __float2half_rn(v.w);
    }
    for (int i = tid; i < NE; i += 256) cnS[i] = g_cnorm[i];
    for (int i = tid; i < TM; i += 256) sCnt[i] = 0;

    // B staging: thread -> code row jrow = tid>>2, k-offset (tid&3)*16; 32 B
    const int jrow = tid >> 2;
    const int kq   = tid & 3;
    const uint32_t bsBase = smem_u32(smem + OFF_BS);
    const uint32_t bsDst  = (uint32_t)(jrow * 144 + kq * 32);

    // issue chunk 0
    {
        const __half* src = g_cbh + (size_t)jrow * D + kq * 16;   // j0=0,k0=0
        cp_async16(bsBase + bsDst,      src);
        cp_async16(bsBase + bsDst + 16, src + 8);
        CP_COMMIT();
    }
    __syncthreads();   // As, cnS, sCnt visible

    float acc[8][4];   // [mt*4+nt][d0..d3]
    #pragma unroll
    for (int i = 0; i < 8; i++)
        #pragma unroll
        for (int c = 0; c < 4; c++) acc[i][c] = 0.f;

    float curMin[4] = {3.4e38f, 3.4e38f, 3.4e38f, 3.4e38f};  // [mt*2 + rowhalf]

    for (int g = 0; g < NCHUNK; g++) {
        const int jt = g >> 2;
        const int kc = g & 3;

        CP_WAIT0();        // chunk g's copy done (this thread's part)
        __syncthreads();   // all threads' copies done; stage (g+1)&1 free

        // issue chunk g+1 (overlaps compute of g)
        if (g + 1 < NCHUNK) {
            const int j0n = ((g + 1) >> 2) * JT;
            const int kbn = ((g + 1) & 3) * KC;
            const __half* src = g_cbh + (size_t)(j0n + jrow) * D + kbn + kq * 16;
            uint32_t dst = bsBase + (uint32_t)(((g + 1) & 1) * BS_SZ) + bsDst;
            cp_async16(dst,      src);
            cp_async16(dst + 16, src + 8);
            CP_COMMIT();
        }

        // compute chunk g from stage g&1
        const uint32_t* Bs = (const uint32_t*)(smem + OFF_BS + (g & 1) * BS_SZ);
        #pragma unroll
        for (int s = 0; s < 4; s++) {
            uint32_t a[2][4];
            #pragma unroll
            for (int mt = 0; mt < 2; mt++) {
                const int base = (mbase + mt * 16 + r) * AS_PITCH_U + kc * 32 + s * 8 + q;
                a[mt][0] = As_u[base];
                a[mt][1] = As_u[base + 8 * AS_PITCH_U];
                a[mt][2] = As_u[base + 4];
                a[mt][3] = As_u[base + 8 * AS_PITCH_U + 4];
            }
            #pragma unroll
            for (int nt = 0; nt < 4; nt++) {
                const int jn = nblk * 32 + nt * 8 + (lane >> 2);
                uint32_t b0 = Bs[jn * BS_PITCH_U + s * 8 + q];
                uint32_t b1 = Bs[jn * BS_PITCH_U + s * 8 + q + 4];
                #pragma unroll
                for (int mt = 0; mt < 2; mt++) {
                    float* d = acc[mt * 4 + nt];
                    mma_h16(d[0], d[1], d[2], d[3],
                            a[mt][0], a[mt][1], a[mt][2], a[mt][3], b0, b1);
                }
            }
        }

        // end of j-tile: running-min update + candidate pushes
        if (kc == 3) {
            const int jcol0 = jt * JT + nblk * 32 + 2 * q;
            float mn[4] = {3.4e38f, 3.4e38f, 3.4e38f, 3.4e38f};
            #pragma unroll
            for (int mt = 0; mt < 2; mt++)
                #pragma unroll
                for (int nt = 0; nt < 4; nt++) {
                    int j = jcol0 + nt * 8;
                    float c0 = cnS[j], c1 = cnS[j + 1];
                    float* d = acc[mt * 4 + nt];
                    mn[mt * 2 + 0] = fminf(mn[mt * 2 + 0], fminf(c0 + d[0], c1 + d[1]));
                    mn[mt * 2 + 1] = fminf(mn[mt * 2 + 1], fminf(c0 + d[2], c1 + d[3]));
                }
            // quad reduce over q (lanes r*4 .. r*4+3 consecutive)
            #pragma unroll
            for (int i = 0; i < 4; i++) {
                mn[i] = fminf(mn[i], __shfl_xor_sync(0xffffffffu, mn[i], 1));
                mn[i] = fminf(mn[i], __shfl_xor_sync(0xffffffffu, mn[i], 2));
                curMin[i] = fminf(curMin[i], mn[i]);
            }
            #pragma unroll
            for (int mt = 0; mt < 2; mt++) {
                const int tA = mbase + mt * 16 + r;
                const int tB = tA + 8;
                const float thrA = curMin[mt * 2 + 0] + MARGIN;
                const float thrB = curMin[mt * 2 + 1] + MARGIN;
                #pragma unroll
                for (int nt = 0; nt < 4; nt++) {
                    int j = jcol0 + nt * 8;
                    float c0 = cnS[j], c1 = cnS[j + 1];
                    float* d = acc[mt * 4 + nt];
                    if (c0 + d[0] < thrA) {
                        int pos = atomicAdd(&sCnt[tA], 1);
                        if (pos < KCAND) sCand[tA * KCAND + pos] = (unsigned short)j;
                    }
                    if (c1 + d[1] < thrA) {
                        int pos = atomicAdd(&sCnt[tA], 1);
                        if (pos < KCAND) sCand[tA * KCAND + pos] = (unsigned short)(j + 1);
                    }
                    if (c0 + d[2] < thrB) {
                        int pos = atomicAdd(&sCnt[tB], 1);
                        if (pos < KCAND) sCand[tB * KCAND + pos] = (unsigned short)j;
                    }
                    if (c1 + d[3] < thrB) {
                        int pos = atomicAdd(&sCnt[tB], 1);
                        if (pos < KCAND) sCand[tB * KCAND + pos] = (unsigned short)(j + 1);
                    }
                    d[0] = d[1] = d[2] = d[3] = 0.f;
                }
            }
        }
    }

    // write lists to global (coalesced)
    __syncthreads();
    for (int i = tid; i < TM; i += 256) g_cnt[n0 + i] = sCnt[i];
    {
        const uint32_t* cu = (const uint32_t*)sCand;                 // [128][KCAND/2]
        uint32_t* gu = (uint32_t*)g_cand + (size_t)n0 * (KCAND / 2);
        for (int i = tid; i < TM * (KCAND / 2); i += 256) gu[i] = cu[i];
    }
}

// ---------------------------------------------------------------------------
// Kernel 3 (pass 2): exact argmin over candidate lists (fp32 rescore).
// Block = 32 tokens; warp = 4 tokens. Lists unsorted -> full comparator.
// Overflowed tokens (cnt > KCAND) fall back to exact full scan.
// ---------------------------------------------------------------------------
__global__ void __launch_bounds__(256) argmin_kernel(const float* __restrict__ z,
                                                     const float* __restrict__ cb,
                                                     float* __restrict__ dout) {
    __shared__ float zs[32][260];
    const int tid  = threadIdx.x;
    const int w    = tid >> 5;
    const int lane = tid & 31;

    const int n0  = blockIdx.x * 32;
    const int b   = n0 >> 12;
    const int hw0 = n0 & (HW - 1);

    for (int i = tid; i < D * 32 / 4; i += 256) {
        int k  = i >> 3;
        int t4 = (i & 7) * 4;
        float4 v = *(const float4*)(z + (size_t)b * CC * HW + (size_t)k * HW + hw0 + t4);
        zs[t4 + 0][k] = v.x; zs[t4 + 1][k] = v.y;
        zs[t4 + 2][k] = v.z; zs[t4 + 3][k] = v.w;
    }
    __syncthreads();

    for (int tt = 0; tt < 4; tt++) {
        const int t = w * 4 + tt;
        const int n = n0 + t;
        const int cnt = g_cnt[n];

        float best = 3.4e38f;
        int   bi   = 0;
        if (cnt <= KCAND) {
            const unsigned short* lst = g_cand + (size_t)n * KCAND;
            for (int ci = 0; ci < cnt; ci++) {
                int j = lst[ci];
                const float* crow = cb + (size_t)j * D;
                float s = 0.f;
                #pragma unroll
                for (int u = 0; u < 8; u++)
                    s = fmaf(zs[t][lane + 32 * u], crow[lane + 32 * u], s);
                #pragma unroll
                for (int o = 16; o; o >>= 1) s += __shfl_xor_sync(0xffffffffu, s, o);
                float dist = g_cnorm[j] - 2.0f * s;
                if (dist < best || (dist == best && j < bi)) { best = dist; bi = j; }
            }
        } else {
            for (int j = 0; j < NE; j++) {
                const float* crow = cb + (size_t)j * D;
                float s = 0.f;
                #pragma unroll
                for (int u = 0; u < 8; u++)
                    s = fmaf(zs[t][lane + 32 * u], crow[lane + 32 * u], s);
                #pragma unroll
                for (int o = 16; o; o >>= 1) s += __shfl_xor_sync(0xffffffffu, s, o);
                float dist = g_cnorm[j] - 2.0f * s;
                if (dist < best) { best = dist; bi = j; }
            }
        }
        if (lane == 0) {
            g_idx[n] = bi;
            dout[IDX_OFF + n] = (float)bi;
        }
    }
}

// ---------------------------------------------------------------------------
// Kernel 4: gather z_q + straight-through output + partial loss
// ---------------------------------------------------------------------------
#define GTOK 32
__global__ void __launch_bounds__(256) gather_kernel(const float* __restrict__ z,
                                                     const float* __restrict__ cb,
                                                     float* __restrict__ dout) {
    __shared__ float zq[GTOK][257];
    __shared__ int   idxs[GTOK];
    __shared__ float ws[8];

    const int tid = threadIdx.x;
    const int n0  = blockIdx.x * GTOK;
    const int b   = n0 / HW;
    const int hw0 = n0 % HW;

    if (tid < GTOK) idxs[tid] = g_idx[n0 + tid];
    __syncthreads();

    #pragma unroll 4
    for (int t = 0; t < GTOK; t++) {
        zq[t][tid] = cb[(size_t)idxs[t] * D + tid];
    }
    __syncthreads();

    const int t  = tid & 31;
    const int c0 = tid >> 5;
    float s = 0.f;
    const float* zb = z    + (size_t)b * CC * HW + hw0 + t;
    float*       ob = dout + (size_t)b * CC * HW + hw0 + t;
    #pragma unroll 8
    for (int it = 0; it < 32; it++) {
        int c = c0 * 32 + it;
        float zv = zb[(size_t)c * HW];
        float d  = zq[t][c] - zv;
        ob[(size_t)c * HW] = zv + d;   // z + sg(z_q - z), exact fp32 expr
        s = fmaf(d, d, s);
    }

    #pragma unroll
    for (int o = 16; o; o >>= 1) s += __shfl_xor_sync(0xffffffffu, s, o);
    if ((tid & 31) == 0) ws[tid >> 5] = s;
    __syncthreads();
    if (tid < 8) {
        float v = ws[tid];
        #pragma unroll
        for (int o = 4; o; o >>= 1) v += __shfl_xor_sync(0xffu, v, o);
        if (tid == 0) g_partial[blockIdx.x] = v;
    }
}

// ---------------------------------------------------------------------------
// Kernel 5: deterministic final reduction
// ---------------------------------------------------------------------------
__global__ void __launch_bounds__(256) finalize_kernel(float* __restrict__ dout) {
    __shared__ float sh[256];
    float s = 0.f;
    for (int i = threadIdx.x; i < GRID_C; i += 256) s += g_partial[i];
    sh[threadIdx.x] = s;
    __syncthreads();
    for (int o = 128; o; o >>= 1) {
        if (threadIdx.x < o) sh[threadIdx.x] += sh[threadIdx.x + o];
        __syncthreads();
    }
    if (threadIdx.x == 0) {
        dout[LOSS_OFF] = sh[0] * (2.0f / (float)ZQ_ELEMS);
        dout[CLS_OFF]  = 0.0f;
    }
}

// ---------------------------------------------------------------------------
extern "C" void kernel_launch(void* const* d_in, const int* in_sizes, int n_in,
                              void* d_out, int out_size) {
    const float* z  = (const float*)d_in[0];   // [B,C,H,W] fp32
    const float* cb = (const float*)d_in[1];   // [NE, D]   fp32
    float* out = (float*)d_out;

    cudaFuncSetAttribute(dist_kernel,
                         cudaFuncAttributeMaxDynamicSharedMemorySize, P1_SMEM);

    cnorm_kernel <<<NE / 8, 256>>>(cb);
    dist_kernel  <<<NTOK / TM, 256, P1_SMEM>>>(z);
    argmin_kernel<<<NTOK / 32, 256>>>(z, cb, out);
    gather_kernel<<<NTOK / GTOK, 256>>>(z, cb, out);
    finalize_kernel<<<1, 256>>>(out);
}

// round 14
// speedup vs baseline: 1.3704x; 1.0136x over previous
#include <cuda_runtime.h>
#include <cuda_fp16.h>
#include <cstdint>

// Problem constants
#define B_    16
#define CC    256
#define HW    4096
#define NTOK  65536
#define NE    1024
#define D     256
#define ZQ_ELEMS (NTOK * CC)
#define LOSS_OFF ZQ_ELEMS
#define CLS_OFF  (ZQ_ELEMS + 1)
#define IDX_OFF  (ZQ_ELEMS + 2)
#define GRID_C 2048

#define MARGIN 1.0f      // > 2x worst-case fp16 screening error; validated R8/R10/R13
#define KCAND  64        // per-token candidate cap (expected ~18)

// Pass-1 tiling: CTA = 128 tokens x NE codes, j-tiles of 64, k-chunks of 64
// Warp tile: m32 x n32 (4 m-blocks x 2 n-blocks = 8 warps)
#define TM   128
#define JT   64
#define KC   64
#define NCHUNK 64            // 16 j-tiles * 4 k-chunks

// Pass-1 smem layout (bytes)
#define AS_PITCH_H 264       // halves per token row (256 + 8 pad)
#define AS_PITCH_U 132
#define OFF_AS 0             // half As[128][264] = 67584
#define BS_PITCH_U 36        // uint (half2) per code row (32 + 4 pad); 144 B
#define BS_SZ  9216          // 64 * 36 * 4
#define OFF_BS 67584         // two cp.async stages
#define OFF_CN (67584 + 2 * BS_SZ)     // 86016
#define OFF_CNT (OFF_CN + 4096)        // 90112 : int cnt[128]
#define OFF_CAND (OFF_CNT + 512)       // 90624 : ushort cand[128][KCAND]
#define P1_SMEM (OFF_CAND + TM * KCAND * 2)   // 107008 -> 2 CTAs/SM

// Scratch (static device arrays are the sanctioned workaround)
__device__ int            g_cnt[NTOK];
__device__ unsigned short g_cand[(size_t)NTOK * KCAND];   // 8 MB
__device__ int            g_idx[NTOK];
__device__ float          g_cnorm[NE];
__device__ float          g_partial[GRID_C];
__device__ __half         g_cbh[(size_t)NE * D];          // -2*codebook, fp16

// ---------------------------------------------------------------------------
// helpers
// ---------------------------------------------------------------------------
__device__ __forceinline__ uint32_t smem_u32(const void* p) {
    uint32_t a;
    asm("{ .reg .u64 t; cvta.to.shared.u64 t, %1; cvt.u32.u64 %0, t; }"
        : "=r"(a) : "l"(p));
    return a;
}
__device__ __forceinline__ void mma_h16(float& d0, float& d1, float& d2, float& d3,
                                        uint32_t a0, uint32_t a1, uint32_t a2, uint32_t a3,
                                        uint32_t b0, uint32_t b1) {
    asm volatile(
        "mma.sync.aligned.m16n8k16.row.col.f32.f16.f16.f32 "
        "{%0,%1,%2,%3}, {%4,%5,%6,%7}, {%8,%9}, {%0,%1,%2,%3};\n"
        : "+f"(d0), "+f"(d1), "+f"(d2), "+f"(d3)
        : "r"(a0), "r"(a1), "r"(a2), "r"(a3), "r"(b0), "r"(b1));
}
__device__ __forceinline__ void cp_async16(uint32_t dst, const void* src) {
    asm volatile("cp.async.cg.shared.global [%0], [%1], 16;"
                 :: "r"(dst), "l"(src) : "memory");
}
#define CP_COMMIT() asm volatile("cp.async.commit_group;" ::: "memory")
#define CP_WAIT0()  asm volatile("cp.async.wait_group 0;" ::: "memory")

// ---------------------------------------------------------------------------
// Kernel 1: per-code squared norms + fp16 pre-scaled codebook (-2*c)
// ---------------------------------------------------------------------------
__global__ void __launch_bounds__(256) cnorm_kernel(const float* __restrict__ cb) {
    int row  = blockIdx.x * 8 + (threadIdx.x >> 5);
    int lane = threadIdx.x & 31;
    const float* p = cb + (size_t)row * D;
    float s = 0.f;
    for (int k = lane; k < D; k += 32) {
        float v = p[k];
        s = fmaf(v, v, s);
        g_cbh[(size_t)row * D + k] = __float2half_rn(-2.f * v);
    }
    #pragma unroll
    for (int o = 16; o; o >>= 1) s += __shfl_xor_sync(0xffffffffu, s, o);
    if (lane == 0) g_cnorm[row] = s;
}

// ---------------------------------------------------------------------------
// Kernel 2 (pass 1): fp16 HMMA screening + fused candidate selection.
// (unchanged from R13 -- at the fallback-HMMA tensor floor)
// ---------------------------------------------------------------------------
__global__ void __launch_bounds__(256, 2) dist_kernel(const float* __restrict__ z) {
    extern __shared__ char smem[];
    __half*         As_h  = (__half*)(smem + OFF_AS);
    uint32_t*       As_u  = (uint32_t*)(smem + OFF_AS);
    float*          cnS   = (float*)(smem + OFF_CN);
    int*            sCnt  = (int*)(smem + OFF_CNT);
    unsigned short* sCand = (unsigned short*)(smem + OFF_CAND);

    const int tid  = threadIdx.x;
    const int w    = tid >> 5;
    const int lane = tid & 31;
    const int r    = lane >> 2;      // row-in-frag 0..7
    const int q    = lane & 3;       // quad column 0..3

    const int mbase = (w & 3) * 32;  // warp's 32-token block
    const int nblk  = w >> 2;        // warp's 32-code half of the j-tile

    const int n0  = blockIdx.x * TM;
    const int b   = n0 >> 12;
    const int rem = n0 & (HW - 1);

    // Stage A: z[b, k, rem+t] -> half As[t][k]  (coalesced loads over t)
    for (int i = tid; i < D * TM / 4; i += 256) {
        int k  = i >> 5;
        int t4 = (i & 31) * 4;
        float4 v = *(const float4*)(z + (size_t)b * CC * HW + (size_t)k * HW + rem + t4);
        As_h[(t4 + 0) * AS_PITCH_H + k] = __float2half_rn(v.x);
        As_h[(t4 + 1) * AS_PITCH_H + k] = __float2half_rn(v.y);
        As_h[(t4 + 2) * AS_PITCH_H + k] = __float2half_rn(v.z);
        As_h[(t4 + 3) * AS_PITCH_H + k] = __float2half_rn(v.w);
    }
    for (int i = tid; i < NE; i += 256) cnS[i] = g_cnorm[i];
    for (int i = tid; i < TM; i += 256) sCnt[i] = 0;

    // B staging: thread -> code row jrow = tid>>2, k-offset (tid&3)*16; 32 B
    const int jrow = tid >> 2;
    const int kq   = tid & 3;
    const uint32_t bsBase = smem_u32(smem + OFF_BS);
    const uint32_t bsDst  = (uint32_t)(jrow * 144 + kq * 32);

    // issue chunk 0
    {
        const __half* src = g_cbh + (size_t)jrow * D + kq * 16;   // j0=0,k0=0
        cp_async16(bsBase + bsDst,      src);
        cp_async16(bsBase + bsDst + 16, src + 8);
        CP_COMMIT();
    }
    __syncthreads();   // As, cnS, sCnt visible

    float acc[8][4];   // [mt*4+nt][d0..d3]
    #pragma unroll
    for (int i = 0; i < 8; i++)
        #pragma unroll
        for (int c = 0; c < 4; c++) acc[i][c] = 0.f;

    float curMin[4] = {3.4e38f, 3.4e38f, 3.4e38f, 3.4e38f};  // [mt*2 + rowhalf]

    for (int g = 0; g < NCHUNK; g++) {
        const int jt = g >> 2;
        const int kc = g & 3;

        CP_WAIT0();        // chunk g's copy done (this thread's part)
        __syncthreads();   // all threads' copies done; stage (g+1)&1 free

        // issue chunk g+1 (overlaps compute of g)
        if (g + 1 < NCHUNK) {
            const int j0n = ((g + 1) >> 2) * JT;
            const int kbn = ((g + 1) & 3) * KC;
            const __half* src = g_cbh + (size_t)(j0n + jrow) * D + kbn + kq * 16;
            uint32_t dst = bsBase + (uint32_t)(((g + 1) & 1) * BS_SZ) + bsDst;
            cp_async16(dst,      src);
            cp_async16(dst + 16, src + 8);
            CP_COMMIT();
        }

        // compute chunk g from stage g&1
        const uint32_t* Bs = (const uint32_t*)(smem + OFF_BS + (g & 1) * BS_SZ);
        #pragma unroll
        for (int s = 0; s < 4; s++) {
            uint32_t a[2][4];
            #pragma unroll
            for (int mt = 0; mt < 2; mt++) {
                const int base = (mbase + mt * 16 + r) * AS_PITCH_U + kc * 32 + s * 8 + q;
                a[mt][0] = As_u[base];
                a[mt][1] = As_u[base + 8 * AS_PITCH_U];
                a[mt][2] = As_u[base + 4];
                a[mt][3] = As_u[base + 8 * AS_PITCH_U + 4];
            }
            #pragma unroll
            for (int nt = 0; nt < 4; nt++) {
                const int jn = nblk * 32 + nt * 8 + (lane >> 2);
                uint32_t b0 = Bs[jn * BS_PITCH_U + s * 8 + q];
                uint32_t b1 = Bs[jn * BS_PITCH_U + s * 8 + q + 4];
                #pragma unroll
                for (int mt = 0; mt < 2; mt++) {
                    float* d = acc[mt * 4 + nt];
                    mma_h16(d[0], d[1], d[2], d[3],
                            a[mt][0], a[mt][1], a[mt][2], a[mt][3], b0, b1);
                }
            }
        }

        // end of j-tile: running-min update + candidate pushes
        if (kc == 3) {
            const int jcol0 = jt * JT + nblk * 32 + 2 * q;
            float mn[4] = {3.4e38f, 3.4e38f, 3.4e38f, 3.4e38f};
            #pragma unroll
            for (int mt = 0; mt < 2; mt++)
                #pragma unroll
                for (int nt = 0; nt < 4; nt++) {
                    int j = jcol0 + nt * 8;
                    float c0 = cnS[j], c1 = cnS[j + 1];
                    float* d = acc[mt * 4 + nt];
                    mn[mt * 2 + 0] = fminf(mn[mt * 2 + 0], fminf(c0 + d[0], c1 + d[1]));
                    mn[mt * 2 + 1] = fminf(mn[mt * 2 + 1], fminf(c0 + d[2], c1 + d[3]));
                }
            // quad reduce over q (lanes r*4 .. r*4+3 consecutive)
            #pragma unroll
            for (int i = 0; i < 4; i++) {
                mn[i] = fminf(mn[i], __shfl_xor_sync(0xffffffffu, mn[i], 1));
                mn[i] = fminf(mn[i], __shfl_xor_sync(0xffffffffu, mn[i], 2));
                curMin[i] = fminf(curMin[i], mn[i]);
            }
            #pragma unroll
            for (int mt = 0; mt < 2; mt++) {
                const int tA = mbase + mt * 16 + r;
                const int tB = tA + 8;
                const float thrA = curMin[mt * 2 + 0] + MARGIN;
                const float thrB = curMin[mt * 2 + 1] + MARGIN;
                #pragma unroll
                for (int nt = 0; nt < 4; nt++) {
                    int j = jcol0 + nt * 8;
                    float c0 = cnS[j], c1 = cnS[j + 1];
                    float* d = acc[mt * 4 + nt];
                    if (c0 + d[0] < thrA) {
                        int pos = atomicAdd(&sCnt[tA], 1);
                        if (pos < KCAND) sCand[tA * KCAND + pos] = (unsigned short)j;
                    }
                    if (c1 + d[1] < thrA) {
                        int pos = atomicAdd(&sCnt[tA], 1);
                        if (pos < KCAND) sCand[tA * KCAND + pos] = (unsigned short)(j + 1);
                    }
                    if (c0 + d[2] < thrB) {
                        int pos = atomicAdd(&sCnt[tB], 1);
                        if (pos < KCAND) sCand[tB * KCAND + pos] = (unsigned short)j;
                    }
                    if (c1 + d[3] < thrB) {
                        int pos = atomicAdd(&sCnt[tB], 1);
                        if (pos < KCAND) sCand[tB * KCAND + pos] = (unsigned short)(j + 1);
                    }
                    d[0] = d[1] = d[2] = d[3] = 0.f;
                }
            }
        }
    }

    // write lists to global (coalesced)
    __syncthreads();
    for (int i = tid; i < TM; i += 256) g_cnt[n0 + i] = sCnt[i];
    {
        const uint32_t* cu = (const uint32_t*)sCand;                 // [128][KCAND/2]
        uint32_t* gu = (uint32_t*)g_cand + (size_t)n0 * (KCAND / 2);
        for (int i = tid; i < TM * (KCAND / 2); i += 256) gu[i] = cu[i];
    }
}

// ---------------------------------------------------------------------------
// Kernel 3 (pass 2): exact argmin over candidate lists, 4-way ILP rescore.
// Per-candidate dot order and warp-reduce sequence are IDENTICAL to R13
// (bitwise-identical distances -> identical indices); 4 independent FMA
// chains share each zs load and keep 4 cb-row LDGs in flight.
// ---------------------------------------------------------------------------
__global__ void __launch_bounds__(256) argmin_kernel(const float* __restrict__ z,
                                                     const float* __restrict__ cb,
                                                     float* __restrict__ dout) {
    __shared__ float zs[32][260];
    const int tid  = threadIdx.x;
    const int w    = tid >> 5;
    const int lane = tid & 31;

    const int n0  = blockIdx.x * 32;
    const int b   = n0 >> 12;
    const int hw0 = n0 & (HW - 1);

    for (int i = tid; i < D * 32 / 4; i += 256) {
        int k  = i >> 3;
        int t4 = (i & 7) * 4;
        float4 v = *(const float4*)(z + (size_t)b * CC * HW + (size_t)k * HW + hw0 + t4);
        zs[t4 + 0][k] = v.x; zs[t4 + 1][k] = v.y;
        zs[t4 + 2][k] = v.z; zs[t4 + 3][k] = v.w;
    }
    __syncthreads();

    for (int tt = 0; tt < 4; tt++) {
        const int t = w * 4 + tt;
        const int n = n0 + t;
        const int cnt = g_cnt[n];

        float best = 3.4e38f;
        int   bi   = 0;
        if (cnt <= KCAND) {
            const unsigned short* lst = g_cand + (size_t)n * KCAND;
            int ci = 0;
            for (; ci + 4 <= cnt; ci += 4) {
                int j0 = lst[ci], j1 = lst[ci + 1], j2 = lst[ci + 2], j3 = lst[ci + 3];
                const float* c0 = cb + (size_t)j0 * D;
                const float* c1 = cb + (size_t)j1 * D;
                const float* c2 = cb + (size_t)j2 * D;
                const float* c3 = cb + (size_t)j3 * D;
                float s0 = 0.f, s1 = 0.f, s2 = 0.f, s3 = 0.f;
                #pragma unroll
                for (int u = 0; u < 8; u++) {
                    float zv = zs[t][lane + 32 * u];
                    s0 = fmaf(zv, c0[lane + 32 * u], s0);
                    s1 = fmaf(zv, c1[lane + 32 * u], s1);
                    s2 = fmaf(zv, c2[lane + 32 * u], s2);
                    s3 = fmaf(zv, c3[lane + 32 * u], s3);
                }
                #pragma unroll
                for (int o = 16; o; o >>= 1) s0 += __shfl_xor_sync(0xffffffffu, s0, o);
                #pragma unroll
                for (int o = 16; o; o >>= 1) s1 += __shfl_xor_sync(0xffffffffu, s1, o);
                #pragma unroll
                for (int o = 16; o; o >>= 1) s2 += __shfl_xor_sync(0xffffffffu, s2, o);
                #pragma unroll
                for (int o = 16; o; o >>= 1) s3 += __shfl_xor_sync(0xffffffffu, s3, o);
                float d0 = g_cnorm[j0] - 2.0f * s0;
                float d1 = g_cnorm[j1] - 2.0f * s1;
                float d2 = g_cnorm[j2] - 2.0f * s2;
                float d3 = g_cnorm[j3] - 2.0f * s3;
                if (d0 < best || (d0 == best && j0 < bi)) { best = d0; bi = j0; }
                if (d1 < best || (d1 == best && j1 < bi)) { best = d1; bi = j1; }
                if (d2 < best || (d2 == best && j2 < bi)) { best = d2; bi = j2; }
                if (d3 < best || (d3 == best && j3 < bi)) { best = d3; bi = j3; }
            }
            for (; ci < cnt; ci++) {
                int j = lst[ci];
                const float* crow = cb + (size_t)j * D;
                float s = 0.f;
                #pragma unroll
                for (int u = 0; u < 8; u++)
                    s = fmaf(zs[t][lane + 32 * u], crow[lane + 32 * u], s);
                #pragma unroll
                for (int o = 16; o; o >>= 1) s += __shfl_xor_sync(0xffffffffu, s, o);
                float dist = g_cnorm[j] - 2.0f * s;
                if (dist < best || (dist == best && j < bi)) { best = dist; bi = j; }
            }
        } else {
            // exact full scan (rare overflow fallback); ascending j, strict <
            for (int j = 0; j < NE; j++) {
                const float* crow = cb + (size_t)j * D;
                float s = 0.f;
                #pragma unroll
                for (int u = 0; u < 8; u++)
                    s = fmaf(zs[t][lane + 32 * u], crow[lane + 32 * u], s);
                #pragma unroll
                for (int o = 16; o; o >>= 1) s += __shfl_xor_sync(0xffffffffu, s, o);
                float dist = g_cnorm[j] - 2.0f * s;
                if (dist < best) { best = dist; bi = j; }
            }
        }
        if (lane == 0) {
            g_idx[n] = bi;
            dout[IDX_OFF + n] = (float)bi;
        }
    }
}

// ---------------------------------------------------------------------------
// Kernel 4: gather z_q + straight-through output + partial loss.
// float4 over the token dim on both z loads and out stores (128B segments,
// 4x MLP); zq held TRANSPOSED [c][t] (pitch 36) so the float4 smem reads
// are aligned and conflict-free. Element expressions identical to R13.
// ---------------------------------------------------------------------------
#define GTOK 32
#define ZQ_PITCH 36
__global__ void __launch_bounds__(256) gather_kernel(const float* __restrict__ z,
                                                     const float* __restrict__ cb,
                                                     float* __restrict__ dout) {
    __shared__ float zq[CC][ZQ_PITCH];   // [c][t], 36 KB
    __shared__ int   idxs[GTOK];
    __shared__ float ws[8];

    const int tid = threadIdx.x;
    const int n0  = blockIdx.x * GTOK;
    const int b   = n0 / HW;
    const int hw0 = n0 % HW;

    if (tid < GTOK) idxs[tid] = g_idx[n0 + tid];
    __syncthreads();

    // stage zq transposed: thread i -> token t = i>>6, channels c4..c4+3
    #pragma unroll
    for (int l = 0; l < 8; l++) {
        int i  = tid + l * 256;
        int t  = i >> 6;
        int c4 = (i & 63) * 4;
        float4 v = *(const float4*)(cb + (size_t)idxs[t] * D + c4);
        zq[c4 + 0][t] = v.x; zq[c4 + 1][t] = v.y;
        zq[c4 + 2][t] = v.z; zq[c4 + 3][t] = v.w;
    }
    __syncthreads();

    const int lane = tid & 31;
    const int w    = tid >> 5;
    const int t4   = (lane & 7) * 4;   // 4 consecutive tokens
    const int cg   = lane >> 3;        // 0..3
    float s = 0.f;
    const float* zbase = z    + (size_t)b * CC * HW + hw0 + t4;
    float*       obase = dout + (size_t)b * CC * HW + hw0 + t4;

    #pragma unroll
    for (int pass = 0; pass < 8; pass++) {
        int c = pass * 32 + w * 4 + cg;
        float4 zv = *(const float4*)(zbase + (size_t)c * HW);
        float4 qv = *(const float4*)(&zq[c][t4]);
        float4 o;
        float d0 = qv.x - zv.x; o.x = zv.x + d0; s = fmaf(d0, d0, s);
        float d1 = qv.y - zv.y; o.y = zv.y + d1; s = fmaf(d1, d1, s);
        float d2 = qv.z - zv.z; o.z = zv.z + d2; s = fmaf(d2, d2, s);
        float d3 = qv.w - zv.w; o.w = zv.w + d3; s = fmaf(d3, d3, s);
        *(float4*)(obase + (size_t)c * HW) = o;
    }

    #pragma unroll
    for (int o = 16; o; o >>= 1) s += __shfl_xor_sync(0xffffffffu, s, o);
    if (lane == 0) ws[w] = s;
    __syncthreads();
    if (tid < 8) {
        float v = ws[tid];
        #pragma unroll
        for (int o = 4; o; o >>= 1) v += __shfl_xor_sync(0xffu, v, o);
        if (tid == 0) g_partial[blockIdx.x] = v;
    }
}

// ---------------------------------------------------------------------------
// Kernel 5: deterministic final reduction
// ---------------------------------------------------------------------------
__global__ void __launch_bounds__(256) finalize_kernel(float* __restrict__ dout) {
    __shared__ float sh[256];
    float s = 0.f;
    for (int i = threadIdx.x; i < GRID_C; i += 256) s += g_partial[i];
    sh[threadIdx.x] = s;
    __syncthreads();
    for (int o = 128; o; o >>= 1) {
        if (threadIdx.x < o) sh[threadIdx.x] += sh[threadIdx.x + o];
        __syncthreads();
    }
    if (threadIdx.x == 0) {
        dout[LOSS_OFF] = sh[0] * (2.0f / (float)ZQ_ELEMS);
        dout[CLS_OFF]  = 0.0f;
    }
}

// ---------------------------------------------------------------------------
extern "C" void kernel_launch(void* const* d_in, const int* in_sizes, int n_in,
                              void* d_out, int out_size) {
    const float* z  = (const float*)d_in[0];   // [B,C,H,W] fp32
    const float* cb = (const float*)d_in[1];   // [NE, D]   fp32
    float* out = (float*)d_out;

    cudaFuncSetAttribute(dist_kernel,
                         cudaFuncAttributeMaxDynamicSharedMemorySize, P1_SMEM);

    cnorm_kernel <<<NE / 8, 256>>>(cb);
    dist_kernel  <<<NTOK / TM, 256, P1_SMEM>>>(z);
    argmin_kernel<<<NTOK / 32, 256>>>(z, cb, out);
    gather_kernel<<<NTOK / GTOK, 256>>>(z, cb, out);
    finalize_kernel<<<1, 256>>>(out);
}

// round 15
// speedup vs baseline: 1.6309x; 1.1901x over previous
#include <cuda_runtime.h>
#include <cuda_fp16.h>
#include <cstdint>

// Problem constants
#define B_    16
#define CC    256
#define HW    4096
#define NTOK  65536
#define NE    1024
#define D     256
#define ZQ_ELEMS (NTOK * CC)
#define LOSS_OFF ZQ_ELEMS
#define CLS_OFF  (ZQ_ELEMS + 1)
#define IDX_OFF  (ZQ_ELEMS + 2)
#define GRID_C 2048

#define MARGIN_I8 3.0f   // ~10x screening-error std; rescore pass stays exact
#define KCAND  64        // per-token candidate cap

// Pass-1 tiling: CTA = 128 tokens x NE codes, j-tiles of 64, k-chunks of 64
// Warp tile m32 x n32 (4 m-blocks x 2 n-blocks = 8 warps); imma m16n8k32
#define TM   128
#define JT   64
#define KC   64
#define NCHUNK 64            // 16 j-tiles * 4 k-chunks

// Pass-1 smem layout (bytes)
#define AS_PITCH_B 272       // int8 bytes per token row (256 + 16 pad)
#define AS_PITCH_W 68        // words
#define OFF_AS 0             // int8 As[128][272] = 34816
#define BS_PITCH_B 80        // int8 bytes per code row (64 + 16 pad) - conflict-free
#define BS_PITCH_W 20
#define BS_SZ  5120          // 64 * 80
#define OFF_BS 34816         // two cp.async stages -> +10240
#define OFF_CN 45056         // float cn[1024]
#define OFF_CM 49152         // float cmax[1024]
#define OFF_FT 53248         // float ft[128]  (-2*mz/16129)
#define OFF_QS 53760         // float qs[128]  (127/mz)
#define OFF_MZP 54272        // float mzpart[8][128]
#define OFF_CNT 58368        // int cnt[128]
#define OFF_CAND 58880       // ushort cand[128][KCAND]
#define P1_SMEM (OFF_CAND + TM * KCAND * 2)   // 75264 -> 2+ CTAs/SM

// Scratch (static device arrays are the sanctioned workaround)
__device__ int            g_cnt[NTOK];
__device__ unsigned short g_cand[(size_t)NTOK * KCAND];   // 8 MB
__device__ int            g_idx[NTOK];
__device__ float          g_cnorm[NE];
__device__ float          g_cmax[NE];
__device__ float          g_partial[GRID_C];
__device__ int8_t         g_cbi8[(size_t)NE * D];         // per-row int8 codebook

// ---------------------------------------------------------------------------
// helpers
// ---------------------------------------------------------------------------
__device__ __forceinline__ uint32_t smem_u32(const void* p) {
    uint32_t a;
    asm("{ .reg .u64 t; cvta.to.shared.u64 t, %1; cvt.u32.u64 %0, t; }"
        : "=r"(a) : "l"(p));
    return a;
}
__device__ __forceinline__ void mma_i8(int& d0, int& d1, int& d2, int& d3,
                                       uint32_t a0, uint32_t a1, uint32_t a2, uint32_t a3,
                                       uint32_t b0, uint32_t b1) {
    asm volatile(
        "mma.sync.aligned.m16n8k32.row.col.s32.s8.s8.s32 "
        "{%0,%1,%2,%3}, {%4,%5,%6,%7}, {%8,%9}, {%0,%1,%2,%3};\n"
        : "+r"(d0), "+r"(d1), "+r"(d2), "+r"(d3)
        : "r"(a0), "r"(a1), "r"(a2), "r"(a3), "r"(b0), "r"(b1));
}
__device__ __forceinline__ void cp_async16(uint32_t dst, const void* src) {
    asm volatile("cp.async.cg.shared.global [%0], [%1], 16;"
                 :: "r"(dst), "l"(src) : "memory");
}
#define CP_COMMIT() asm volatile("cp.async.commit_group;" ::: "memory")
#define CP_WAIT0()  asm volatile("cp.async.wait_group 0;" ::: "memory")

// ---------------------------------------------------------------------------
// Kernel 1: per-code norms, absmax, and int8-quantized codebook
// ---------------------------------------------------------------------------
__global__ void __launch_bounds__(256) cnorm_kernel(const float* __restrict__ cb) {
    int row  = blockIdx.x * 8 + (threadIdx.x >> 5);
    int lane = threadIdx.x & 31;
    const float* p = cb + (size_t)row * D;
    float v[8];
    float s = 0.f, m = 0.f;
    #pragma unroll
    for (int u = 0; u < 8; u++) {
        v[u] = p[lane + 32 * u];
        s = fmaf(v[u], v[u], s);
        m = fmaxf(m, fabsf(v[u]));
    }
    #pragma unroll
    for (int o = 16; o; o >>= 1) {
        s += __shfl_xor_sync(0xffffffffu, s, o);
        m = fmaxf(m, __shfl_xor_sync(0xffffffffu, m, o));
    }
    m = fmaxf(m, 1e-20f);
    if (lane == 0) { g_cnorm[row] = s; g_cmax[row] = m; }
    float qsc = 127.0f / m;
    #pragma unroll
    for (int u = 0; u < 8; u++)
        g_cbi8[(size_t)row * D + lane + 32 * u] = (int8_t)__float2int_rn(v[u] * qsc);
}

// ---------------------------------------------------------------------------
// Kernel 2 (pass 1): int8 IMMA screening + fused candidate selection.
// Per-token / per-code scales; d_approx = cn[j] + ft[t]*cm[j]*S_int.
// Margin-rescore (pass 2) keeps the final argmin exact.
// ---------------------------------------------------------------------------
__global__ void __launch_bounds__(256, 2) dist_kernel(const float* __restrict__ z) {
    extern __shared__ char smem[];
    int8_t*         As8   = (int8_t*)(smem + OFF_AS);
    uint32_t*       As_u  = (uint32_t*)(smem + OFF_AS);
    float*          cnS   = (float*)(smem + OFF_CN);
    float*          cmS   = (float*)(smem + OFF_CM);
    float*          ftS   = (float*)(smem + OFF_FT);
    float*          qsS   = (float*)(smem + OFF_QS);
    float*          mzp   = (float*)(smem + OFF_MZP);
    int*            sCnt  = (int*)(smem + OFF_CNT);
    unsigned short* sCand = (unsigned short*)(smem + OFF_CAND);

    const int tid  = threadIdx.x;
    const int w    = tid >> 5;
    const int lane = tid & 31;
    const int r    = lane >> 2;      // row-in-frag 0..7
    const int q    = lane & 3;       // quad column 0..3

    const int mbase = (w & 3) * 32;  // warp's 32-token block
    const int nblk  = w >> 2;        // warp's 32-code half of the j-tile

    const int n0  = blockIdx.x * TM;
    const int b   = n0 >> 12;
    const int rem = n0 & (HW - 1);
    const float* zb = z + (size_t)b * CC * HW + rem;

    // ---- A staging pass 1: per-token absmax ----
    const int t4 = (tid & 31) * 4;   // this thread's 4 tokens
    float m4[4] = {0.f, 0.f, 0.f, 0.f};
    #pragma unroll 8
    for (int l = 0; l < 32; l++) {
        int k = w + 8 * l;
        float4 v = *(const float4*)(zb + (size_t)k * HW + t4);
        m4[0] = fmaxf(m4[0], fabsf(v.x));
        m4[1] = fmaxf(m4[1], fabsf(v.y));
        m4[2] = fmaxf(m4[2], fabsf(v.z));
        m4[3] = fmaxf(m4[3], fabsf(v.w));
    }
    #pragma unroll
    for (int j = 0; j < 4; j++) mzp[w * 128 + t4 + j] = m4[j];
    for (int i = tid; i < NE; i += 256) { cnS[i] = g_cnorm[i]; cmS[i] = g_cmax[i]; }
    for (int i = tid; i < TM; i += 256) sCnt[i] = 0;
    __syncthreads();

    if (tid < TM) {
        float mz = 0.f;
        #pragma unroll
        for (int ww = 0; ww < 8; ww++) mz = fmaxf(mz, mzp[ww * 128 + tid]);
        mz = fmaxf(mz, 1e-20f);
        ftS[tid] = -2.0f * mz / 16129.0f;
        qsS[tid] = 127.0f / mz;
    }
    __syncthreads();

    // ---- A staging pass 2: quantize (z re-read is L2-hot) ----
    {
        float q0 = qsS[t4], q1 = qsS[t4 + 1], q2 = qsS[t4 + 2], q3 = qsS[t4 + 3];
        #pragma unroll 8
        for (int l = 0; l < 32; l++) {
            int k = w + 8 * l;
            float4 v = *(const float4*)(zb + (size_t)k * HW + t4);
            As8[(t4 + 0) * AS_PITCH_B + k] = (int8_t)__float2int_rn(v.x * q0);
            As8[(t4 + 1) * AS_PITCH_B + k] = (int8_t)__float2int_rn(v.y * q1);
            As8[(t4 + 2) * AS_PITCH_B + k] = (int8_t)__float2int_rn(v.z * q2);
            As8[(t4 + 3) * AS_PITCH_B + k] = (int8_t)__float2int_rn(v.w * q3);
        }
    }

    // ---- B staging: thread -> code row tid>>2, 16B quarter (tid&3) ----
    const int jrow = tid >> 2;
    const int kq   = tid & 3;
    const uint32_t bsBase = smem_u32(smem + OFF_BS);
    const uint32_t bsDst  = (uint32_t)(jrow * BS_PITCH_B + kq * 16);
    cp_async16(bsBase + bsDst, g_cbi8 + (size_t)jrow * D + kq * 16);   // chunk 0
    CP_COMMIT();
    __syncthreads();   // As, scales visible

    int acc[8][4];   // [mt*4+nt][c0..c3]
    #pragma unroll
    for (int i = 0; i < 8; i++)
        #pragma unroll
        for (int c = 0; c < 4; c++) acc[i][c] = 0;

    float curMin[4] = {3.4e38f, 3.4e38f, 3.4e38f, 3.4e38f};  // [mt*2 + rowhalf]

    for (int g = 0; g < NCHUNK; g++) {
        const int jt = g >> 2;
        const int kc = g & 3;

        CP_WAIT0();
        __syncthreads();

        if (g + 1 < NCHUNK) {
            const int j0n = ((g + 1) >> 2) * JT;
            const int kbn = ((g + 1) & 3) * KC;
            uint32_t dst = bsBase + (uint32_t)(((g + 1) & 1) * BS_SZ) + bsDst;
            cp_async16(dst, g_cbi8 + (size_t)(j0n + jrow) * D + kbn + kq * 16);
            CP_COMMIT();
        }

        // compute chunk g (2 k32 steps)
        const uint32_t* Bs = (const uint32_t*)(smem + OFF_BS + (g & 1) * BS_SZ);
        #pragma unroll
        for (int ks = 0; ks < 2; ks++) {
            uint32_t a[2][4];
            #pragma unroll
            for (int mt = 0; mt < 2; mt++) {
                const int base = (mbase + mt * 16 + r) * AS_PITCH_W + kc * 16 + ks * 8 + q;
                a[mt][0] = As_u[base];
                a[mt][1] = As_u[base + 8 * AS_PITCH_W];
                a[mt][2] = As_u[base + 4];
                a[mt][3] = As_u[base + 4 + 8 * AS_PITCH_W];
            }
            #pragma unroll
            for (int nt = 0; nt < 4; nt++) {
                const int jn = nblk * 32 + nt * 8 + (lane >> 2);
                uint32_t b0 = Bs[jn * BS_PITCH_W + ks * 8 + q];
                uint32_t b1 = Bs[jn * BS_PITCH_W + ks * 8 + q + 4];
                #pragma unroll
                for (int mt = 0; mt < 2; mt++) {
                    int* d = acc[mt * 4 + nt];
                    mma_i8(d[0], d[1], d[2], d[3],
                           a[mt][0], a[mt][1], a[mt][2], a[mt][3], b0, b1);
                }
            }
        }

        // end of j-tile: scale to float, running-min, candidate pushes
        if (kc == 3) {
            const int jcol0 = jt * JT + nblk * 32 + 2 * q;
            float vv[8][4];
            #pragma unroll
            for (int mt = 0; mt < 2; mt++) {
                const int tA = mbase + mt * 16 + r;
                const float fA = ftS[tA], fB = ftS[tA + 8];
                #pragma unroll
                for (int nt = 0; nt < 4; nt++) {
                    int j = jcol0 + nt * 8;
                    float sc0 = cmS[j], sc1 = cmS[j + 1];
                    float c0 = cnS[j],  c1 = cnS[j + 1];
                    int* d = acc[mt * 4 + nt];
                    vv[mt * 4 + nt][0] = fmaf(fA * sc0, (float)d[0], c0);
                    vv[mt * 4 + nt][1] = fmaf(fA * sc1, (float)d[1], c1);
                    vv[mt * 4 + nt][2] = fmaf(fB * sc0, (float)d[2], c0);
                    vv[mt * 4 + nt][3] = fmaf(fB * sc1, (float)d[3], c1);
                    d[0] = d[1] = d[2] = d[3] = 0;
                }
            }
            float mn[4] = {3.4e38f, 3.4e38f, 3.4e38f, 3.4e38f};
            #pragma unroll
            for (int mt = 0; mt < 2; mt++)
                #pragma unroll
                for (int nt = 0; nt < 4; nt++) {
                    float* d = vv[mt * 4 + nt];
                    mn[mt * 2 + 0] = fminf(mn[mt * 2 + 0], fminf(d[0], d[1]));
                    mn[mt * 2 + 1] = fminf(mn[mt * 2 + 1], fminf(d[2], d[3]));
                }
            #pragma unroll
            for (int i = 0; i < 4; i++) {
                mn[i] = fminf(mn[i], __shfl_xor_sync(0xffffffffu, mn[i], 1));
                mn[i] = fminf(mn[i], __shfl_xor_sync(0xffffffffu, mn[i], 2));
                curMin[i] = fminf(curMin[i], mn[i]);
            }
            #pragma unroll
            for (int mt = 0; mt < 2; mt++) {
                const int tA = mbase + mt * 16 + r;
                const int tB = tA + 8;
                const float thrA = curMin[mt * 2 + 0] + MARGIN_I8;
                const float thrB = curMin[mt * 2 + 1] + MARGIN_I8;
                #pragma unroll
                for (int nt = 0; nt < 4; nt++) {
                    int j = jcol0 + nt * 8;
                    float* d = vv[mt * 4 + nt];
                    if (d[0] < thrA) {
                        int pos = atomicAdd(&sCnt[tA], 1);
                        if (pos < KCAND) sCand[tA * KCAND + pos] = (unsigned short)j;
                    }
                    if (d[1] < thrA) {
                        int pos = atomicAdd(&sCnt[tA], 1);
                        if (pos < KCAND) sCand[tA * KCAND + pos] = (unsigned short)(j + 1);
                    }
                    if (d[2] < thrB) {
                        int pos = atomicAdd(&sCnt[tB], 1);
                        if (pos < KCAND) sCand[tB * KCAND + pos] = (unsigned short)j;
                    }
                    if (d[3] < thrB) {
                        int pos = atomicAdd(&sCnt[tB], 1);
                        if (pos < KCAND) sCand[tB * KCAND + pos] = (unsigned short)(j + 1);
                    }
                }
            }
        }
    }

    // write lists to global (coalesced)
    __syncthreads();
    for (int i = tid; i < TM; i += 256) g_cnt[n0 + i] = sCnt[i];
    {
        const uint32_t* cu = (const uint32_t*)sCand;
        uint32_t* gu = (uint32_t*)g_cand + (size_t)n0 * (KCAND / 2);
        for (int i = tid; i < TM * (KCAND / 2); i += 256) gu[i] = cu[i];
    }
}

// ---------------------------------------------------------------------------
// Kernel 3 (pass 2): exact argmin over candidate lists, 4-way ILP rescore.
// (R14-measured; per-candidate arithmetic identical across rounds)
// ---------------------------------------------------------------------------
__global__ void __launch_bounds__(256) argmin_kernel(const float* __restrict__ z,
                                                     const float* __restrict__ cb,
                                                     float* __restrict__ dout) {
    __shared__ float zs[32][260];
    const int tid  = threadIdx.x;
    const int w    = tid >> 5;
    const int lane = tid & 31;

    const int n0  = blockIdx.x * 32;
    const int b   = n0 >> 12;
    const int hw0 = n0 & (HW - 1);

    for (int i = tid; i < D * 32 / 4; i += 256) {
        int k  = i >> 3;
        int t4 = (i & 7) * 4;
        float4 v = *(const float4*)(z + (size_t)b * CC * HW + (size_t)k * HW + hw0 + t4);
        zs[t4 + 0][k] = v.x; zs[t4 + 1][k] = v.y;
        zs[t4 + 2][k] = v.z; zs[t4 + 3][k] = v.w;
    }
    __syncthreads();

    for (int tt = 0; tt < 4; tt++) {
        const int t = w * 4 + tt;
        const int n = n0 + t;
        const int cnt = g_cnt[n];

        float best = 3.4e38f;
        int   bi   = 0;
        if (cnt <= KCAND) {
            const unsigned short* lst = g_cand + (size_t)n * KCAND;
            int ci = 0;
            for (; ci + 4 <= cnt; ci += 4) {
                int j0 = lst[ci], j1 = lst[ci + 1], j2 = lst[ci + 2], j3 = lst[ci + 3];
                const float* c0 = cb + (size_t)j0 * D;
                const float* c1 = cb + (size_t)j1 * D;
                const float* c2 = cb + (size_t)j2 * D;
                const float* c3 = cb + (size_t)j3 * D;
                float s0 = 0.f, s1 = 0.f, s2 = 0.f, s3 = 0.f;
                #pragma unroll
                for (int u = 0; u < 8; u++) {
                    float zv = zs[t][lane + 32 * u];
                    s0 = fmaf(zv, c0[lane + 32 * u], s0);
                    s1 = fmaf(zv, c1[lane + 32 * u], s1);
                    s2 = fmaf(zv, c2[lane + 32 * u], s2);
                    s3 = fmaf(zv, c3[lane + 32 * u], s3);
                }
                #pragma unroll
                for (int o = 16; o; o >>= 1) s0 += __shfl_xor_sync(0xffffffffu, s0, o);
                #pragma unroll
                for (int o = 16; o; o >>= 1) s1 += __shfl_xor_sync(0xffffffffu, s1, o);
                #pragma unroll
                for (int o = 16; o; o >>= 1) s2 += __shfl_xor_sync(0xffffffffu, s2, o);
                #pragma unroll
                for (int o = 16; o; o >>= 1) s3 += __shfl_xor_sync(0xffffffffu, s3, o);
                float d0 = g_cnorm[j0] - 2.0f * s0;
                float d1 = g_cnorm[j1] - 2.0f * s1;
                float d2 = g_cnorm[j2] - 2.0f * s2;
                float d3 = g_cnorm[j3] - 2.0f * s3;
                if (d0 < best || (d0 == best && j0 < bi)) { best = d0; bi = j0; }
                if (d1 < best || (d1 == best && j1 < bi)) { best = d1; bi = j1; }
                if (d2 < best || (d2 == best && j2 < bi)) { best = d2; bi = j2; }
                if (d3 < best || (d3 == best && j3 < bi)) { best = d3; bi = j3; }
            }
            for (; ci < cnt; ci++) {
                int j = lst[ci];
                const float* crow = cb + (size_t)j * D;
                float s = 0.f;
                #pragma unroll
                for (int u = 0; u < 8; u++)
                    s = fmaf(zs[t][lane + 32 * u], crow[lane + 32 * u], s);
                #pragma unroll
                for (int o = 16; o; o >>= 1) s += __shfl_xor_sync(0xffffffffu, s, o);
                float dist = g_cnorm[j] - 2.0f * s;
                if (dist < best || (dist == best && j < bi)) { best = dist; bi = j; }
            }
        } else {
            for (int j = 0; j < NE; j++) {
                const float* crow = cb + (size_t)j * D;
                float s = 0.f;
                #pragma unroll
                for (int u = 0; u < 8; u++)
                    s = fmaf(zs[t][lane + 32 * u], crow[lane + 32 * u], s);
                #pragma unroll
                for (int o = 16; o; o >>= 1) s += __shfl_xor_sync(0xffffffffu, s, o);
                float dist = g_cnorm[j] - 2.0f * s;
                if (dist < best) { best = dist; bi = j; }
            }
        }
        if (lane == 0) {
            g_idx[n] = bi;
            dout[IDX_OFF + n] = (float)bi;
        }
    }
}

// ---------------------------------------------------------------------------
// Kernel 4: gather (REVERTED to R13-measured 39.8us version)
// ---------------------------------------------------------------------------
#define GTOK 32
__global__ void __launch_bounds__(256) gather_kernel(const float* __restrict__ z,
                                                     const float* __restrict__ cb,
                                                     float* __restrict__ dout) {
    __shared__ float zq[GTOK][257];
    __shared__ int   idxs[GTOK];
    __shared__ float ws[8];

    const int tid = threadIdx.x;
    const int n0  = blockIdx.x * GTOK;
    const int b   = n0 / HW;
    const int hw0 = n0 % HW;

    if (tid < GTOK) idxs[tid] = g_idx[n0 + tid];
    __syncthreads();

    #pragma unroll 4
    for (int t = 0; t < GTOK; t++) {
        zq[t][tid] = cb[(size_t)idxs[t] * D + tid];
    }
    __syncthreads();

    const int t  = tid & 31;
    const int c0 = tid >> 5;
    float s = 0.f;
    const float* zb = z    + (size_t)b * CC * HW + hw0 + t;
    float*       ob = dout + (size_t)b * CC * HW + hw0 + t;
    #pragma unroll 8
    for (int it = 0; it < 32; it++) {
        int c = c0 * 32 + it;
        float zv = zb[(size_t)c * HW];
        float d  = zq[t][c] - zv;
        ob[(size_t)c * HW] = zv + d;   // z + sg(z_q - z), exact fp32 expr
        s = fmaf(d, d, s);
    }

    #pragma unroll
    for (int o = 16; o; o >>= 1) s += __shfl_xor_sync(0xffffffffu, s, o);
    if ((tid & 31) == 0) ws[tid >> 5] = s;
    __syncthreads();
    if (tid < 8) {
        float v = ws[tid];
        #pragma unroll
        for (int o = 4; o; o >>= 1) v += __shfl_xor_sync(0xffu, v, o);
        if (tid == 0) g_partial[blockIdx.x] = v;
    }
}

// ---------------------------------------------------------------------------
// Kernel 5: deterministic final reduction
// ---------------------------------------------------------------------------
__global__ void __launch_bounds__(256) finalize_kernel(float* __restrict__ dout) {
    __shared__ float sh[256];
    float s = 0.f;
    for (int i = threadIdx.x; i < GRID_C; i += 256) s += g_partial[i];
    sh[threadIdx.x] = s;
    __syncthreads();
    for (int o = 128; o; o >>= 1) {
        if (threadIdx.x < o) sh[threadIdx.x] += sh[threadIdx.x + o];
        __syncthreads();
    }
    if (threadIdx.x == 0) {
        dout[LOSS_OFF] = sh[0] * (2.0f / (float)ZQ_ELEMS);
        dout[CLS_OFF]  = 0.0f;
    }
}

// ---------------------------------------------------------------------------
extern "C" void kernel_launch(void* const* d_in, const int* in_sizes, int n_in,
                              void* d_out, int out_size) {
    const float* z  = (const float*)d_in[0];   // [B,C,H,W] fp32
    const float* cb = (const float*)d_in[1];   // [NE, D]   fp32
    float* out = (float*)d_out;

    cudaFuncSetAttribute(dist_kernel,
                         cudaFuncAttributeMaxDynamicSharedMemorySize, P1_SMEM);

    cnorm_kernel <<<NE / 8, 256>>>(cb);
    dist_kernel  <<<NTOK / TM, 256, P1_SMEM>>>(z);
    argmin_kernel<<<NTOK / 32, 256>>>(z, cb, out);
    gather_kernel<<<NTOK / GTOK, 256>>>(z, cb, out);
    finalize_kernel<<<1, 256>>>(out);
}